// round 9
// baseline (speedup 1.0000x reference)
#include <cuda_runtime.h>
#include <math.h>

#define AEMB 16
#define DIN  480
#define NTH  512
#define BM   128

// ---- shared memory layout (float offsets) ----
#define X0_PITCH 129
#define AS_PITCH 17
#define AS_OFF   (BM * X0_PITCH)            // 16512
#define B1_OFF   (AS_OFF + BM * AS_PITCH)   // 18688
#define B2_OFF   (B1_OFF + 128)             // 18816
#define WB_OFF   (B2_OFF + 16)              // 18832 (16B-aligned: *4)
#define WBUF     8256                       // 8 kc-blocks * 1032 (1024 + 8 skew)
#define MID_OFF  (WB_OFF + 2 * WBUF)        // 35344
#define SMEM_FLOATS (MID_OFF + BM * 17)     // 37520
#define SMEM_BYTES  (SMEM_FLOATS * 4)       // 150080

__device__ __forceinline__ unsigned cvt_tf32(float f) {
    unsigned u; asm("cvt.rna.tf32.f32 %0, %1;" : "=r"(u) : "f"(f)); return u;
}
__device__ __forceinline__ void mma_tf32(float* d, unsigned a0, unsigned a1,
                                         unsigned a2, unsigned a3,
                                         unsigned b0, unsigned b1) {
    asm volatile(
        "mma.sync.aligned.m16n8k8.row.col.f32.tf32.tf32.f32 "
        "{%0,%1,%2,%3}, {%4,%5,%6,%7}, {%8,%9}, {%0,%1,%2,%3};"
        : "+f"(d[0]), "+f"(d[1]), "+f"(d[2]), "+f"(d[3])
        : "r"(a0), "r"(a1), "r"(a2), "r"(a3), "r"(b0), "r"(b1));
}
__device__ __forceinline__ float silu_f(float x) { return x / (1.0f + __expf(-x)); }

__global__ void __launch_bounds__(NTH, 1)
tp_head_kernel(const float* __restrict__ nv, const float* __restrict__ ae,
               const float* __restrict__ W1, const float* __restrict__ b1,
               const float* __restrict__ W2, const float* __restrict__ b2,
               const float* __restrict__ W3, const float* __restrict__ b3,
               const float* __restrict__ W4, const float* __restrict__ b4,
               float* __restrict__ out)
{
    extern __shared__ float sm[];
    float* x0s  = sm;                 // [128][129] x0, later scalars
    float* as_  = sm + AS_OFF;        // [128][17]
    float* b1s  = sm + B1_OFF;
    float* b2s  = sm + B2_OFF;
    float* wb   = sm + WB_OFF;        // 2 x WBUF B-staging buffers
    float* mids = sm + MID_OFF;       // [128][17]

    const int tid = threadIdx.x;
    const int wid = tid >> 5;
    const int l   = tid & 31;
    const int n0  = blockIdx.x * BM;
    const int q   = l >> 2;           // 0..7
    const int lk  = l & 3;            // 0..3

    // ---- stage x0 (first 128 cols), a, b1, b2 ----
    for (int t = tid; t < BM * 32; t += NTH) {
        int lr = t >> 5, c4 = (t & 31) << 2;
        float4 v = *(const float4*)(nv + (size_t)(n0 + lr) * DIN + c4);
        float* dst = x0s + lr * X0_PITCH + c4;
        dst[0] = v.x; dst[1] = v.y; dst[2] = v.z; dst[3] = v.w;
    }
    {
        int lr = tid >> 2, c4 = (tid & 3) << 2;  // 512 = 128*4 exactly
        float4 v = *(const float4*)(ae + (size_t)(n0 + lr) * AEMB + c4);
        float* dst = as_ + lr * AS_PITCH + c4;
        dst[0] = v.x; dst[1] = v.y; dst[2] = v.z; dst[3] = v.w;
    }
    if (tid < 128) b1s[tid] = b1[tid];
    if (tid >= 128 && tid < 144) b2s[tid - 128] = b2[tid - 128];

    // ---- phase-1 staging thread mapping ----
    const int cg1 = tid >> 6;        // column group (16 cols), = tp
    const int kl1 = tid & 63;        // k-row within 64-chunk
    const int kc1 = kl1 >> 3, kr1 = kl1 & 7;
    const int lk1 = kr1 & 3, hf1 = kr1 >> 2;
    float* st1base = wb + kc1 * 1032 + cg1 * 128;

    float4 wreg[4];
    {   // prefetch chunk 0
        const float* src = W1 + ((size_t)((kl1 >> 4) * 16 + (kl1 & 15))) * 224 + cg1 * 16;
#pragma unroll
        for (int j = 0; j < 4; ++j) wreg[j] = ((const float4*)src)[j];
    }
    __syncthreads();

    // ---- per-warp MMA geometry: 32 rows (2 strips) x 4 tiles ----
    const int rp = wid >> 2;          // row-pair 0..3 -> rows [rp*32, rp*32+32)
    const int nq = wid & 3;           // tile quad: tiles nq*4..nq*4+3
    float ar[4][4];                   // a[row_j, {lk, lk+4, 8+lk, 12+lk}]
#pragma unroll
    for (int j = 0; j < 4; ++j) {
        int rj = rp * 32 + q + j * 8;
        ar[j][0] = as_[rj * AS_PITCH + lk];
        ar[j][1] = as_[rj * AS_PITCH + lk + 4];
        ar[j][2] = as_[rj * AS_PITCH + lk + 8];
        ar[j][3] = as_[rj * AS_PITCH + lk + 12];
    }

    float acc[8][4];                  // [strip*4 + tile][frag]
#pragma unroll
    for (int t = 0; t < 8; ++t)
#pragma unroll
        for (int e = 0; e < 4; ++e) acc[t][e] = 0.0f;

    // =================== Phase 1: s = (x0 (x) a) @ W1flat ===================
    for (int sc = 0; sc < 32; ++sc) {
        {   // store wreg (chunk sc) -> buf, conflict-free skewed layout
            float* b = st1base + (sc & 1) * WBUF;
            const float* w = (const float*)wreg;
#pragma unroll
            for (int e = 0; e < 16; ++e)
                *(unsigned*)(b + ((e & 7) * 4 + lk1) * 4 + (e >> 3) * 2 + hf1) =
                    cvt_tf32(w[e]);
        }
        if (sc + 1 < 32) {  // prefetch chunk sc+1
            const float* src = W1 +
                ((size_t)(((sc + 1) * 4 + (kl1 >> 4)) * 16 + (kl1 & 15))) * 224 + cg1 * 16;
#pragma unroll
            for (int j = 0; j < 4; ++j) wreg[j] = ((const float4*)src)[j];
        }
        __syncthreads();

        const float* bbase = wb + (sc & 1) * WBUF;
        float xv[4];
#pragma unroll
        for (int kc = 0; kc < 8; ++kc) {
            if ((kc & 1) == 0) {
                int i = sc * 4 + (kc >> 1);
#pragma unroll
                for (int j = 0; j < 4; ++j)
                    xv[j] = x0s[(rp * 32 + q + j * 8) * X0_PITCH + i];
            }
            const int idx0 = (kc & 1) * 2;
            unsigned A0[4], A1[4];
            A0[0] = cvt_tf32(xv[0] * ar[0][idx0]);
            A0[1] = cvt_tf32(xv[1] * ar[1][idx0]);
            A0[2] = cvt_tf32(xv[0] * ar[0][idx0 + 1]);
            A0[3] = cvt_tf32(xv[1] * ar[1][idx0 + 1]);
            A1[0] = cvt_tf32(xv[2] * ar[2][idx0]);
            A1[1] = cvt_tf32(xv[3] * ar[3][idx0]);
            A1[2] = cvt_tf32(xv[2] * ar[2][idx0 + 1]);
            A1[3] = cvt_tf32(xv[3] * ar[3][idx0 + 1]);
#pragma unroll
            for (int j = 0; j < 2; ++j) {
                float4 bv = *((const float4*)(bbase + kc * 1032 + (nq * 2 + j) * 128) + l);
                unsigned b00 = __float_as_uint(bv.x), b01 = __float_as_uint(bv.y);
                unsigned b10 = __float_as_uint(bv.z), b11 = __float_as_uint(bv.w);
                mma_tf32(acc[j * 2 + 0],     A0[0], A0[1], A0[2], A0[3], b00, b01);
                mma_tf32(acc[j * 2 + 1],     A0[0], A0[1], A0[2], A0[3], b10, b11);
                mma_tf32(acc[4 + j * 2 + 0], A1[0], A1[1], A1[2], A1[3], b00, b01);
                mma_tf32(acc[4 + j * 2 + 1], A1[0], A1[1], A1[2], A1[3], b10, b11);
            }
        }
    }
    __syncthreads();   // all warps done reading x0s before scalars overwrite it

    // ---- epilogue 1: scalars = silu(s*INV + b1) -> x0s ----
    const float INV = 0.022097086912079608f;   // 1/sqrt(128*16)
#pragma unroll
    for (int st = 0; st < 2; ++st)
#pragma unroll
        for (int tt = 0; tt < 4; ++tt) {
            int c0 = (nq * 4 + tt) * 8 + lk * 2;
            int row = rp * 32 + st * 16 + q;
            float* a = acc[st * 4 + tt];
            x0s[row * X0_PITCH + c0]           = silu_f(a[0] * INV + b1s[c0]);
            x0s[row * X0_PITCH + c0 + 1]       = silu_f(a[1] * INV + b1s[c0 + 1]);
            x0s[(row + 8) * X0_PITCH + c0]     = silu_f(a[2] * INV + b1s[c0]);
            x0s[(row + 8) * X0_PITCH + c0 + 1] = silu_f(a[3] * INV + b1s[c0 + 1]);
        }

    // ---- phase-2 staging mapping (chunks of 256 k-rows, 8 chunks) ----
    const int cg2 = tid >> 8;         // 0..1 (8 cols each)
    const int kl2 = tid & 255;
    const int kc2 = kl2 >> 3, kr2 = kl2 & 7;
    const int lk2 = kr2 & 3, hf2 = kr2 >> 2;
    float4 w2reg[2];
    {   // prefetch chunk 0
        const float* src = W2 + ((size_t)((kl2 >> 4) * 16 + (kl2 & 15))) * 16 + cg2 * 8;
        w2reg[0] = ((const float4*)src)[0];
        w2reg[1] = ((const float4*)src)[1];
    }
    __syncthreads();

    // ---- phase-2 MMA geometry: 16 rows x 1 tile per warp ----
    const int sW = wid >> 1;          // strip 0..7
    const int th = wid & 1;           // tile 0..1
    float ar2[2][4];
#pragma unroll
    for (int j = 0; j < 2; ++j) {
        int rj = sW * 16 + q + j * 8;
        ar2[j][0] = as_[rj * AS_PITCH + lk];
        ar2[j][1] = as_[rj * AS_PITCH + lk + 4];
        ar2[j][2] = as_[rj * AS_PITCH + lk + 8];
        ar2[j][3] = as_[rj * AS_PITCH + lk + 12];
    }
    float acc2[4] = {0.0f, 0.0f, 0.0f, 0.0f};

    for (int cN = 0; cN < 8; ++cN) {
        {   // store chunk cN
            float* b = wb + (cN & 1) * WBUF + kc2 * 136;
            const float* w = (const float*)w2reg;
#pragma unroll
            for (int e = 0; e < 8; ++e)
                *(unsigned*)(b + (e * 4 + lk2) * 4 + cg2 * 2 + hf2) = cvt_tf32(w[e]);
        }
        if (cN + 1 < 8) {
            const float* src = W2 +
                ((size_t)(((cN + 1) * 16 + (kl2 >> 4)) * 16 + (kl2 & 15))) * 16 + cg2 * 8;
            w2reg[0] = ((const float4*)src)[0];
            w2reg[1] = ((const float4*)src)[1];
        }
        __syncthreads();

        const float* bbase = wb + (cN & 1) * WBUF;
        float xv2[2];
#pragma unroll 8
        for (int kc = 0; kc < 32; ++kc) {
            if ((kc & 1) == 0) {
                int i = cN * 16 + (kc >> 1);
                xv2[0] = x0s[(sW * 16 + q) * X0_PITCH + i];
                xv2[1] = x0s[(sW * 16 + 8 + q) * X0_PITCH + i];
            }
            const int idx0 = (kc & 1) * 2;
            unsigned a0 = cvt_tf32(xv2[0] * ar2[0][idx0]);
            unsigned a1 = cvt_tf32(xv2[1] * ar2[1][idx0]);
            unsigned a2 = cvt_tf32(xv2[0] * ar2[0][idx0 + 1]);
            unsigned a3 = cvt_tf32(xv2[1] * ar2[1][idx0 + 1]);
            float2 bv = *(const float2*)(bbase + kc * 136 + l * 4 + th * 2);
            mma_tf32(acc2, a0, a1, a2, a3,
                     __float_as_uint(bv.x), __float_as_uint(bv.y));
        }
    }
    // epilogue 2
    {
        int c0 = th * 8 + lk * 2;
        int row = sW * 16 + q;
        mids[row * 17 + c0]           = acc2[0] * INV + b2s[c0];
        mids[row * 17 + c0 + 1]       = acc2[1] * INV + b2s[c0 + 1];
        mids[(row + 8) * 17 + c0]     = acc2[2] * INV + b2s[c0];
        mids[(row + 8) * 17 + c0 + 1] = acc2[3] * INV + b2s[c0 + 1];
    }
    __syncthreads();

    // stage W3/W4/b3/b4 into wb (free now)
    if (tid < 256) wb[tid] = W3[tid];
    if (tid >= 256 && tid < 272) wb[tid] = W4[tid - 256];
    if (tid >= 288 && tid < 304) wb[tid] = b3[tid - 288];
    if (tid == 304) wb[304] = b4[0];
    __syncthreads();

    // =================== Phase 3: tiny 16x16 head ===================
    if (tid < BM) {
        float mv[16];
#pragma unroll
        for (int j = 0; j < 16; ++j) mv[j] = mids[tid * 17 + j];
        float o = 0.0f;
#pragma unroll
        for (int jo = 0; jo < 16; ++jo) {
            float t = 0.0f;
#pragma unroll
            for (int ji = 0; ji < 16; ++ji) t += mv[ji] * wb[ji * 16 + jo];
            t = t * 0.25f + wb[288 + jo];
            o += silu_f(t) * wb[256 + jo];
        }
        out[n0 + tid] = o * 0.25f + wb[304];
    }
}

extern "C" void kernel_launch(void* const* d_in, const int* in_sizes, int n_in,
                              void* d_out, int out_size) {
    const float* nv = (const float*)d_in[0];
    const float* ae = (const float*)d_in[1];
    const float* W1 = (const float*)d_in[2];
    // d_in[3], d_in[4] dead (W1_l1, W1_l2)
    const float* b1 = (const float*)d_in[5];
    const float* W2 = (const float*)d_in[6];
    const float* b2 = (const float*)d_in[7];
    const float* W3 = (const float*)d_in[8];
    const float* b3 = (const float*)d_in[9];
    const float* W4 = (const float*)d_in[10];
    const float* b4 = (const float*)d_in[11];
    float* out = (float*)d_out;

    int nodes = in_sizes[1] / AEMB;
    int grid  = nodes / BM;

    cudaFuncSetAttribute(tp_head_kernel,
                         cudaFuncAttributeMaxDynamicSharedMemorySize, SMEM_BYTES);
    tp_head_kernel<<<grid, NTH, SMEM_BYTES>>>(nv, ae, W1, b1, W2, b2,
                                              W3, b3, W4, b4, out);
}

// round 10
// speedup vs baseline: 1.0027x; 1.0027x over previous
#include <cuda_runtime.h>
#include <math.h>

#define AEMB 16
#define DIN  480
#define NTH  512
#define BM   128

// ---- shared memory layout (float offsets) ----
#define X0_PITCH 129
#define AS_PITCH 17
#define AS_OFF   (BM * X0_PITCH)            // 16512
#define B1_OFF   (AS_OFF + BM * AS_PITCH)   // 18688
#define B2_OFF   (B1_OFF + 128)             // 18816
#define WB_OFF   (B2_OFF + 16)              // 18832 (16B-aligned: *4)
#define WBUF     8256                       // 8 kc-blocks * 1032 (1024 + 8 skew)
#define MID_OFF  (WB_OFF + 2 * WBUF)        // 35344
#define SMEM_FLOATS (MID_OFF + BM * 17)     // 37520
#define SMEM_BYTES  (SMEM_FLOATS * 4)       // 150080

__device__ __forceinline__ unsigned cvt_tf32(float f) {
    unsigned u; asm("cvt.rna.tf32.f32 %0, %1;" : "=r"(u) : "f"(f)); return u;
}
__device__ __forceinline__ void mma_tf32(float* d, unsigned a0, unsigned a1,
                                         unsigned a2, unsigned a3,
                                         unsigned b0, unsigned b1) {
    asm volatile(
        "mma.sync.aligned.m16n8k8.row.col.f32.tf32.tf32.f32 "
        "{%0,%1,%2,%3}, {%4,%5,%6,%7}, {%8,%9}, {%0,%1,%2,%3};"
        : "+f"(d[0]), "+f"(d[1]), "+f"(d[2]), "+f"(d[3])
        : "r"(a0), "r"(a1), "r"(a2), "r"(a3), "r"(b0), "r"(b1));
}
__device__ __forceinline__ float silu_f(float x) { return x / (1.0f + __expf(-x)); }

__global__ void __launch_bounds__(NTH, 1)
tp_head_kernel(const float* __restrict__ nv, const float* __restrict__ ae,
               const float* __restrict__ W1, const float* __restrict__ b1,
               const float* __restrict__ W2, const float* __restrict__ b2,
               const float* __restrict__ W3, const float* __restrict__ b3,
               const float* __restrict__ W4, const float* __restrict__ b4,
               float* __restrict__ out)
{
    extern __shared__ float sm[];
    float* x0s  = sm;                 // [128][129] x0, later scalars
    float* as_  = sm + AS_OFF;        // [128][17]
    float* b1s  = sm + B1_OFF;
    float* b2s  = sm + B2_OFF;
    float* wb   = sm + WB_OFF;        // 2 x WBUF B-staging buffers
    float* mids = sm + MID_OFF;       // [128][17]

    const int tid = threadIdx.x;
    const int wid = tid >> 5;
    const int l   = tid & 31;
    const int n0  = blockIdx.x * BM;
    const int q   = l >> 2;           // 0..7
    const int lk  = l & 3;            // 0..3

    // ---- stage x0 (first 128 cols), a, b1, b2 ----
    for (int t = tid; t < BM * 32; t += NTH) {
        int lr = t >> 5, c4 = (t & 31) << 2;
        float4 v = *(const float4*)(nv + (size_t)(n0 + lr) * DIN + c4);
        float* dst = x0s + lr * X0_PITCH + c4;
        dst[0] = v.x; dst[1] = v.y; dst[2] = v.z; dst[3] = v.w;
    }
    {
        int lr = tid >> 2, c4 = (tid & 3) << 2;  // 512 = 128*4 exactly
        float4 v = *(const float4*)(ae + (size_t)(n0 + lr) * AEMB + c4);
        float* dst = as_ + lr * AS_PITCH + c4;
        dst[0] = v.x; dst[1] = v.y; dst[2] = v.z; dst[3] = v.w;
    }
    if (tid < 128) b1s[tid] = b1[tid];
    if (tid >= 128 && tid < 144) b2s[tid - 128] = b2[tid - 128];

    // ---- phase-1 staging thread mapping ----
    const int cg1 = tid >> 6;        // column group (16 cols), = tp
    const int kl1 = tid & 63;        // k-row within 64-chunk
    const int kc1 = kl1 >> 3, kr1 = kl1 & 7;
    const int lk1 = kr1 & 3, hf1 = kr1 >> 2;
    float* st1base = wb + kc1 * 1032 + cg1 * 128;

    float4 wreg[4];
    {   // prefetch chunk 0
        const float* src = W1 + ((size_t)((kl1 >> 4) * 16 + (kl1 & 15))) * 224 + cg1 * 16;
#pragma unroll
        for (int j = 0; j < 4; ++j) wreg[j] = ((const float4*)src)[j];
    }
    __syncthreads();

    // ---- per-warp MMA geometry: 32 rows (2 strips) x 4 tiles ----
    const int rp = wid >> 2;          // row-pair 0..3 -> rows [rp*32, rp*32+32)
    const int nq = wid & 3;           // tile quad: tiles nq*4..nq*4+3
    float ar[4][4];                   // a[row_j, {lk, lk+4, 8+lk, 12+lk}]
#pragma unroll
    for (int j = 0; j < 4; ++j) {
        int rj = rp * 32 + q + j * 8;
        ar[j][0] = as_[rj * AS_PITCH + lk];
        ar[j][1] = as_[rj * AS_PITCH + lk + 4];
        ar[j][2] = as_[rj * AS_PITCH + lk + 8];
        ar[j][3] = as_[rj * AS_PITCH + lk + 12];
    }

    float acc[8][4];                  // [strip*4 + tile][frag]
#pragma unroll
    for (int t = 0; t < 8; ++t)
#pragma unroll
        for (int e = 0; e < 4; ++e) acc[t][e] = 0.0f;

    // =================== Phase 1: s = (x0 (x) a) @ W1flat ===================
    for (int sc = 0; sc < 32; ++sc) {
        {   // store wreg (chunk sc) -> buf, conflict-free skewed layout
            float* b = st1base + (sc & 1) * WBUF;
            const float* w = (const float*)wreg;
#pragma unroll
            for (int e = 0; e < 16; ++e)
                *(unsigned*)(b + ((e & 7) * 4 + lk1) * 4 + (e >> 3) * 2 + hf1) =
                    cvt_tf32(w[e]);
        }
        if (sc + 1 < 32) {  // prefetch chunk sc+1
            const float* src = W1 +
                ((size_t)(((sc + 1) * 4 + (kl1 >> 4)) * 16 + (kl1 & 15))) * 224 + cg1 * 16;
#pragma unroll
            for (int j = 0; j < 4; ++j) wreg[j] = ((const float4*)src)[j];
        }
        __syncthreads();

        const float* bbase = wb + (sc & 1) * WBUF;
        float xv[4];
#pragma unroll
        for (int kc = 0; kc < 8; ++kc) {
            if ((kc & 1) == 0) {
                int i = sc * 4 + (kc >> 1);
#pragma unroll
                for (int j = 0; j < 4; ++j)
                    xv[j] = x0s[(rp * 32 + q + j * 8) * X0_PITCH + i];
            }
            const int idx0 = (kc & 1) * 2;
            unsigned A0[4], A1[4];
            A0[0] = cvt_tf32(xv[0] * ar[0][idx0]);
            A0[1] = cvt_tf32(xv[1] * ar[1][idx0]);
            A0[2] = cvt_tf32(xv[0] * ar[0][idx0 + 1]);
            A0[3] = cvt_tf32(xv[1] * ar[1][idx0 + 1]);
            A1[0] = cvt_tf32(xv[2] * ar[2][idx0]);
            A1[1] = cvt_tf32(xv[3] * ar[3][idx0]);
            A1[2] = cvt_tf32(xv[2] * ar[2][idx0 + 1]);
            A1[3] = cvt_tf32(xv[3] * ar[3][idx0 + 1]);
#pragma unroll
            for (int j = 0; j < 2; ++j) {
                float4 bv = *((const float4*)(bbase + kc * 1032 + (nq * 2 + j) * 128) + l);
                unsigned b00 = __float_as_uint(bv.x), b01 = __float_as_uint(bv.y);
                unsigned b10 = __float_as_uint(bv.z), b11 = __float_as_uint(bv.w);
                mma_tf32(acc[j * 2 + 0],     A0[0], A0[1], A0[2], A0[3], b00, b01);
                mma_tf32(acc[j * 2 + 1],     A0[0], A0[1], A0[2], A0[3], b10, b11);
                mma_tf32(acc[4 + j * 2 + 0], A1[0], A1[1], A1[2], A1[3], b00, b01);
                mma_tf32(acc[4 + j * 2 + 1], A1[0], A1[1], A1[2], A1[3], b10, b11);
            }
        }
    }
    __syncthreads();   // all warps done reading x0s before scalars overwrite it

    // ---- epilogue 1: scalars = silu(s*INV + b1) -> x0s ----
    const float INV = 0.022097086912079608f;   // 1/sqrt(128*16)
#pragma unroll
    for (int st = 0; st < 2; ++st)
#pragma unroll
        for (int tt = 0; tt < 4; ++tt) {
            int c0 = (nq * 4 + tt) * 8 + lk * 2;
            int row = rp * 32 + st * 16 + q;
            float* a = acc[st * 4 + tt];
            x0s[row * X0_PITCH + c0]           = silu_f(a[0] * INV + b1s[c0]);
            x0s[row * X0_PITCH + c0 + 1]       = silu_f(a[1] * INV + b1s[c0 + 1]);
            x0s[(row + 8) * X0_PITCH + c0]     = silu_f(a[2] * INV + b1s[c0]);
            x0s[(row + 8) * X0_PITCH + c0 + 1] = silu_f(a[3] * INV + b1s[c0 + 1]);
        }

    // ---- phase-2 staging mapping (chunks of 256 k-rows, 8 chunks) ----
    const int cg2 = tid >> 8;         // 0..1 (8 cols each)
    const int kl2 = tid & 255;
    const int kc2 = kl2 >> 3, kr2 = kl2 & 7;
    const int lk2 = kr2 & 3, hf2 = kr2 >> 2;
    float4 w2reg[2];
    {   // prefetch chunk 0
        const float* src = W2 + ((size_t)((kl2 >> 4) * 16 + (kl2 & 15))) * 16 + cg2 * 8;
        w2reg[0] = ((const float4*)src)[0];
        w2reg[1] = ((const float4*)src)[1];
    }
    __syncthreads();

    // ---- phase-2 MMA geometry: 16 rows x 1 tile per warp ----
    const int sW = wid >> 1;          // strip 0..7
    const int th = wid & 1;           // tile 0..1
    float ar2[2][4];
#pragma unroll
    for (int j = 0; j < 2; ++j) {
        int rj = sW * 16 + q + j * 8;
        ar2[j][0] = as_[rj * AS_PITCH + lk];
        ar2[j][1] = as_[rj * AS_PITCH + lk + 4];
        ar2[j][2] = as_[rj * AS_PITCH + lk + 8];
        ar2[j][3] = as_[rj * AS_PITCH + lk + 12];
    }
    float acc2[4] = {0.0f, 0.0f, 0.0f, 0.0f};

    for (int cN = 0; cN < 8; ++cN) {
        {   // store chunk cN
            float* b = wb + (cN & 1) * WBUF + kc2 * 136;
            const float* w = (const float*)w2reg;
#pragma unroll
            for (int e = 0; e < 8; ++e)
                *(unsigned*)(b + (e * 4 + lk2) * 4 + cg2 * 2 + hf2) = cvt_tf32(w[e]);
        }
        if (cN + 1 < 8) {
            const float* src = W2 +
                ((size_t)(((cN + 1) * 16 + (kl2 >> 4)) * 16 + (kl2 & 15))) * 16 + cg2 * 8;
            w2reg[0] = ((const float4*)src)[0];
            w2reg[1] = ((const float4*)src)[1];
        }
        __syncthreads();

        const float* bbase = wb + (cN & 1) * WBUF;
        float xv2[2];
#pragma unroll 8
        for (int kc = 0; kc < 32; ++kc) {
            if ((kc & 1) == 0) {
                int i = cN * 16 + (kc >> 1);
                xv2[0] = x0s[(sW * 16 + q) * X0_PITCH + i];
                xv2[1] = x0s[(sW * 16 + 8 + q) * X0_PITCH + i];
            }
            const int idx0 = (kc & 1) * 2;
            unsigned a0 = cvt_tf32(xv2[0] * ar2[0][idx0]);
            unsigned a1 = cvt_tf32(xv2[1] * ar2[1][idx0]);
            unsigned a2 = cvt_tf32(xv2[0] * ar2[0][idx0 + 1]);
            unsigned a3 = cvt_tf32(xv2[1] * ar2[1][idx0 + 1]);
            float2 bv = *(const float2*)(bbase + kc * 136 + l * 4 + th * 2);
            mma_tf32(acc2, a0, a1, a2, a3,
                     __float_as_uint(bv.x), __float_as_uint(bv.y));
        }
    }
    // epilogue 2
    {
        int c0 = th * 8 + lk * 2;
        int row = sW * 16 + q;
        mids[row * 17 + c0]           = acc2[0] * INV + b2s[c0];
        mids[row * 17 + c0 + 1]       = acc2[1] * INV + b2s[c0 + 1];
        mids[(row + 8) * 17 + c0]     = acc2[2] * INV + b2s[c0];
        mids[(row + 8) * 17 + c0 + 1] = acc2[3] * INV + b2s[c0 + 1];
    }
    __syncthreads();

    // stage W3/W4/b3/b4 into wb (free now)
    if (tid < 256) wb[tid] = W3[tid];
    if (tid >= 256 && tid < 272) wb[tid] = W4[tid - 256];
    if (tid >= 288 && tid < 304) wb[tid] = b3[tid - 288];
    if (tid == 304) wb[304] = b4[0];
    __syncthreads();

    // =================== Phase 3: tiny 16x16 head ===================
    if (tid < BM) {
        float mv[16];
#pragma unroll
        for (int j = 0; j < 16; ++j) mv[j] = mids[tid * 17 + j];
        float o = 0.0f;
#pragma unroll
        for (int jo = 0; jo < 16; ++jo) {
            float t = 0.0f;
#pragma unroll
            for (int ji = 0; ji < 16; ++ji) t += mv[ji] * wb[ji * 16 + jo];
            t = t * 0.25f + wb[288 + jo];
            o += silu_f(t) * wb[256 + jo];
        }
        out[n0 + tid] = o * 0.25f + wb[304];
    }
}

extern "C" void kernel_launch(void* const* d_in, const int* in_sizes, int n_in,
                              void* d_out, int out_size) {
    const float* nv = (const float*)d_in[0];
    const float* ae = (const float*)d_in[1];
    const float* W1 = (const float*)d_in[2];
    // d_in[3], d_in[4] dead (W1_l1, W1_l2)
    const float* b1 = (const float*)d_in[5];
    const float* W2 = (const float*)d_in[6];
    const float* b2 = (const float*)d_in[7];
    const float* W3 = (const float*)d_in[8];
    const float* b3 = (const float*)d_in[9];
    const float* W4 = (const float*)d_in[10];
    const float* b4 = (const float*)d_in[11];
    float* out = (float*)d_out;

    int nodes = in_sizes[1] / AEMB;
    int grid  = nodes / BM;

    cudaFuncSetAttribute(tp_head_kernel,
                         cudaFuncAttributeMaxDynamicSharedMemorySize, SMEM_BYTES);
    tp_head_kernel<<<grid, NTH, SMEM_BYTES>>>(nv, ae, W1, b1, W2, b2,
                                              W3, b3, W4, b4, out);
}

// round 11
// speedup vs baseline: 1.8116x; 1.8066x over previous
#include <cuda_runtime.h>
#include <math.h>

#define NTH  512
#define AEMB 16
#define DIN  480

// ---- shared memory layout (float offsets) ----
#define X0P  129
#define ASP  17
#define AS_OFF  (128 * X0P)              // 16512
#define B1_OFF  (AS_OFF + 128 * ASP)     // 18688
#define B2_OFF  (B1_OFF + 128)           // 18816
#define WB_OFF  (B2_OFF + 16)            // 18832 (byte 75328, 16B aligned)
#define PB1     8192                     // u32 per phase-1 buffer (8 i x 1024)
#define PB2     2048                     // u32 per phase-2 buffer (16 i x 128)
#define MID_OFF (WB_OFF + 2 * PB1)       // 35216
#define SMEM_FLOATS (MID_OFF + 128 * 17) // 37392
#define SMEM_BYTES  (SMEM_FLOATS * 4)    // 149568

// pack two fp32 -> half2 (lo in low half)
__device__ __forceinline__ unsigned pkh2(float lo, float hi) {
    unsigned d;
    asm("cvt.rn.f16x2.f32 %0, %2, %1;" : "=r"(d) : "f"(lo), "f"(hi));
    return d;
}
__device__ __forceinline__ void mma16(float* d, unsigned a0, unsigned a1,
                                      unsigned a2, unsigned a3,
                                      unsigned b0, unsigned b1) {
    asm volatile(
        "mma.sync.aligned.m16n8k16.row.col.f32.f16.f16.f32 "
        "{%0,%1,%2,%3}, {%4,%5,%6,%7}, {%8,%9}, {%0,%1,%2,%3};"
        : "+f"(d[0]), "+f"(d[1]), "+f"(d[2]), "+f"(d[3])
        : "r"(a0), "r"(a1), "r"(a2), "r"(a3), "r"(b0), "r"(b1));
}
__device__ __forceinline__ float silu_f(float x) { return x / (1.0f + __expf(-x)); }

__global__ void __launch_bounds__(NTH, 1)
tp_head_kernel(const float* __restrict__ nv, const float* __restrict__ ae,
               const float* __restrict__ W1, const float* __restrict__ b1,
               const float* __restrict__ W2, const float* __restrict__ b2,
               const float* __restrict__ W3, const float* __restrict__ b3,
               const float* __restrict__ W4, const float* __restrict__ b4,
               float* __restrict__ out)
{
    extern __shared__ float sm[];
    float*    x0s  = sm;                        // [128][129] x0, later scalars
    float*    as_  = sm + AS_OFF;               // [128][17]
    float*    b1s  = sm + B1_OFF;
    float*    b2s  = sm + B2_OFF;
    unsigned* wb32 = (unsigned*)(sm + WB_OFF);  // fp16-pair B buffers
    float*    wbf  = sm + WB_OFF;               // float view (phase 3)
    float*    mids = sm + MID_OFF;              // [128][17]

    const int tid = threadIdx.x;
    const int wid = tid >> 5;
    const int l   = tid & 31;
    const int n0  = blockIdx.x * 128;
    const int q   = l >> 2;        // 0..7
    const int mk  = l & 3;         // 0..3

    // ---- stage x0 (first 128 cols), a, b1, b2 ----
    for (int t = tid; t < 128 * 32; t += NTH) {
        int lr = t >> 5, c4 = (t & 31) << 2;
        float4 v = *(const float4*)(nv + (size_t)(n0 + lr) * DIN + c4);
        float* dst = x0s + lr * X0P + c4;
        dst[0] = v.x; dst[1] = v.y; dst[2] = v.z; dst[3] = v.w;
    }
    {
        int lr = tid >> 2, c4 = (tid & 3) << 2;
        float4 v = *(const float4*)(ae + (size_t)(n0 + lr) * AEMB + c4);
        float* dst = as_ + lr * ASP + c4;
        dst[0] = v.x; dst[1] = v.y; dst[2] = v.z; dst[3] = v.w;
    }
    if (tid < 128) b1s[tid] = b1[tid];
    if (tid >= 128 && tid < 144) b2s[tid - 128] = b2[tid - 128];

    // ---- phase-1 staging ids ----
    const int i1  = tid >> 6;        // i_loc 0..7
    const int p1  = (tid >> 3) & 7;
    const int nbl = tid & 7;
    const int mk1 = p1 & 3, h1 = p1 >> 2;
    const int aa1 = mk1 * 2 + h1 * 8;     // first of the k-row pair

    // prefetch W1 chunk 0
    float4 v0[4], v1[4];
    {
        const float* rp0 = W1 + ((size_t)(i1 * 16 + aa1)) * 224;
#pragma unroll
        for (int g = 0; g < 4; ++g) {
            int nb = nbl * 4 + g * 32;
            v0[g] = *(const float4*)(rp0 + nb);
            v1[g] = *(const float4*)(rp0 + 224 + nb);
        }
    }
    __syncthreads();

    // ---- MMA geometry: warp = 32 rows (rp) x 32 cols (nq) ----
    const int rp = wid >> 2;
    const int nq = wid & 3;
    float ar[4][4];                 // a[row_j][{2mk,2mk+1,2mk+8,2mk+9}]
#pragma unroll
    for (int j = 0; j < 4; ++j) {
        int rj = rp * 32 + q + j * 8;
        ar[j][0] = as_[rj * ASP + 2 * mk];
        ar[j][1] = as_[rj * ASP + 2 * mk + 1];
        ar[j][2] = as_[rj * ASP + 2 * mk + 8];
        ar[j][3] = as_[rj * ASP + 2 * mk + 9];
    }
    int nsw[4];
#pragma unroll
    for (int t = 0; t < 4; ++t)
        nsw[t] = (nq * 32 + t * 8 + q) ^ (mk << 3);

    float acc[8][4];
#pragma unroll
    for (int t = 0; t < 8; ++t)
#pragma unroll
        for (int e = 0; e < 4; ++e) acc[t][e] = 0.0f;

    // =============== Phase 1: s = (x0 (x) a) @ W1flat, 16 chunks of 8 i ===============
    for (int sc = 0; sc < 16; ++sc) {
        {   // store prefetched chunk sc (fp16 pairs, swizzled, STS.128)
            unsigned* dst = wb32 + (sc & 1) * PB1 + i1 * 1024 + h1 * 512 + mk1 * 128;
#pragma unroll
            for (int g = 0; g < 4; ++g) {
                int nb = nbl * 4 + g * 32;
                uint4 u;
                u.x = pkh2(v0[g].x, v1[g].x);
                u.y = pkh2(v0[g].y, v1[g].y);
                u.z = pkh2(v0[g].z, v1[g].z);
                u.w = pkh2(v0[g].w, v1[g].w);
                *(uint4*)(dst + (nb ^ (mk1 << 3))) = u;
            }
        }
        if (sc + 1 < 16) {  // prefetch chunk sc+1
            const float* rp0 = W1 + ((size_t)(((sc + 1) * 8 + i1) * 16 + aa1)) * 224;
#pragma unroll
            for (int g = 0; g < 4; ++g) {
                int nb = nbl * 4 + g * 32;
                v0[g] = *(const float4*)(rp0 + nb);
                v1[g] = *(const float4*)(rp0 + 224 + nb);
            }
        }
        __syncthreads();

        const unsigned* bb = wb32 + (sc & 1) * PB1;
#pragma unroll 2
        for (int il = 0; il < 8; ++il) {
            int i = sc * 8 + il;
            float x[4];
#pragma unroll
            for (int j = 0; j < 4; ++j)
                x[j] = x0s[(rp * 32 + q + j * 8) * X0P + i];
            unsigned A0[4], A1[4];
            A0[0] = pkh2(x[0] * ar[0][0], x[0] * ar[0][1]);
            A0[1] = pkh2(x[1] * ar[1][0], x[1] * ar[1][1]);
            A0[2] = pkh2(x[0] * ar[0][2], x[0] * ar[0][3]);
            A0[3] = pkh2(x[1] * ar[1][2], x[1] * ar[1][3]);
            A1[0] = pkh2(x[2] * ar[2][0], x[2] * ar[2][1]);
            A1[1] = pkh2(x[3] * ar[3][0], x[3] * ar[3][1]);
            A1[2] = pkh2(x[2] * ar[2][2], x[2] * ar[2][3]);
            A1[3] = pkh2(x[3] * ar[3][2], x[3] * ar[3][3]);
            const unsigned* bp = bb + il * 1024 + mk * 128;
#pragma unroll
            for (int t = 0; t < 4; ++t) {
                unsigned bx0 = bp[nsw[t]];
                unsigned bx1 = bp[512 + nsw[t]];
                mma16(acc[t],     A0[0], A0[1], A0[2], A0[3], bx0, bx1);
                mma16(acc[4 + t], A1[0], A1[1], A1[2], A1[3], bx0, bx1);
            }
        }
        __syncthreads();
    }

    // ---- epilogue 1: scalars = silu(s*INV + b1) -> x0s ----
    const float INV = 0.022097086912079608f;   // 1/sqrt(128*16)
#pragma unroll
    for (int sp = 0; sp < 2; ++sp)
#pragma unroll
        for (int t = 0; t < 4; ++t) {
            int c0 = nq * 32 + t * 8 + mk * 2;
            int row = rp * 32 + sp * 16 + q;
            float* a = acc[sp * 4 + t];
            x0s[row * X0P + c0]           = silu_f(a[0] * INV + b1s[c0]);
            x0s[row * X0P + c0 + 1]       = silu_f(a[1] * INV + b1s[c0 + 1]);
            x0s[(row + 8) * X0P + c0]     = silu_f(a[2] * INV + b1s[c0]);
            x0s[(row + 8) * X0P + c0 + 1] = silu_f(a[3] * INV + b1s[c0 + 1]);
        }

    // ---- phase-2 staging ids ----
    const int i2  = tid >> 5;            // i_loc 0..15
    const int p2  = (tid >> 2) & 7;
    const int nb2 = (tid & 3) * 4;       // n base 0,4,8,12
    const int mk2 = p2 & 3, h2 = p2 >> 2;
    const int aa2 = mk2 * 2 + h2 * 8;
    const int sw2 = (mk2 >> 1) << 3;

    float4 y0, y1;
    y0 = *(const float4*)(W2 + ((size_t)(i2 * 16 + aa2)) * 16 + nb2);
    y1 = *(const float4*)(W2 + ((size_t)(i2 * 16 + aa2 + 1)) * 16 + nb2);

    // ---- phase-2 MMA geometry: warp = 16 rows (sW) x 8 cols (th) ----
    const int sW = wid >> 1;
    const int th = wid & 1;
    float ar2[2][4];
#pragma unroll
    for (int j = 0; j < 2; ++j) {
        int rj = sW * 16 + q + j * 8;
        ar2[j][0] = as_[rj * ASP + 2 * mk];
        ar2[j][1] = as_[rj * ASP + 2 * mk + 1];
        ar2[j][2] = as_[rj * ASP + 2 * mk + 8];
        ar2[j][3] = as_[rj * ASP + 2 * mk + 9];
    }
    const int nsw2 = (th * 8 + q) ^ ((mk >> 1) << 3);
    float acc2[4] = {0.0f, 0.0f, 0.0f, 0.0f};

    // =============== Phase 2: mid = (scal (x) a) @ W2flat, 8 chunks of 16 i ===============
    for (int cN = 0; cN < 8; ++cN) {
        {
            unsigned* dst = wb32 + (cN & 1) * PB2 + i2 * 128 + h2 * 64 + mk2 * 16;
            uint4 u;
            u.x = pkh2(y0.x, y1.x);
            u.y = pkh2(y0.y, y1.y);
            u.z = pkh2(y0.z, y1.z);
            u.w = pkh2(y0.w, y1.w);
            *(uint4*)(dst + (nb2 ^ sw2)) = u;
        }
        if (cN + 1 < 8) {
            const float* src = W2 + ((size_t)(((cN + 1) * 16 + i2) * 16 + aa2)) * 16 + nb2;
            y0 = *(const float4*)(src);
            y1 = *(const float4*)(src + 16);
        }
        __syncthreads();

        const unsigned* bb = wb32 + (cN & 1) * PB2;
#pragma unroll 4
        for (int il = 0; il < 16; ++il) {
            int i = cN * 16 + il;
            float s0 = x0s[(sW * 16 + q) * X0P + i];
            float s1 = x0s[(sW * 16 + 8 + q) * X0P + i];
            unsigned a0 = pkh2(s0 * ar2[0][0], s0 * ar2[0][1]);
            unsigned a1 = pkh2(s1 * ar2[1][0], s1 * ar2[1][1]);
            unsigned a2 = pkh2(s0 * ar2[0][2], s0 * ar2[0][3]);
            unsigned a3 = pkh2(s1 * ar2[1][2], s1 * ar2[1][3]);
            const unsigned* bp = bb + il * 128 + mk * 16;
            mma16(acc2, a0, a1, a2, a3, bp[nsw2], bp[64 + nsw2]);
        }
        __syncthreads();
    }

    // ---- epilogue 2: mids = acc2*INV + b2 ----
    {
        int c0 = th * 8 + mk * 2;
        int row = sW * 16 + q;
        mids[row * 17 + c0]           = acc2[0] * INV + b2s[c0];
        mids[row * 17 + c0 + 1]       = acc2[1] * INV + b2s[c0 + 1];
        mids[(row + 8) * 17 + c0]     = acc2[2] * INV + b2s[c0];
        mids[(row + 8) * 17 + c0 + 1] = acc2[3] * INV + b2s[c0 + 1];
    }
    __syncthreads();

    // stage W3/W4/b3/b4 into wbf (B buffers are dead now)
    if (tid < 256) wbf[tid] = W3[tid];
    if (tid >= 256 && tid < 272) wbf[tid] = W4[tid - 256];
    if (tid >= 288 && tid < 304) wbf[tid] = b3[tid - 288];
    if (tid == 304) wbf[304] = b4[0];
    __syncthreads();

    // =============== Phase 3: tiny 16x16 head ===============
    if (tid < 128) {
        float mv[16];
#pragma unroll
        for (int j = 0; j < 16; ++j) mv[j] = mids[tid * 17 + j];
        float o = 0.0f;
#pragma unroll
        for (int jo = 0; jo < 16; ++jo) {
            float t = 0.0f;
#pragma unroll
            for (int ji = 0; ji < 16; ++ji) t += mv[ji] * wbf[ji * 16 + jo];
            t = t * 0.25f + wbf[288 + jo];
            o += silu_f(t) * wbf[256 + jo];
        }
        out[n0 + tid] = o * 0.25f + wbf[304];
    }
}

extern "C" void kernel_launch(void* const* d_in, const int* in_sizes, int n_in,
                              void* d_out, int out_size) {
    const float* nv = (const float*)d_in[0];
    const float* ae = (const float*)d_in[1];
    const float* W1 = (const float*)d_in[2];
    // d_in[3], d_in[4] dead (W1_l1, W1_l2)
    const float* b1 = (const float*)d_in[5];
    const float* W2 = (const float*)d_in[6];
    const float* b2 = (const float*)d_in[7];
    const float* W3 = (const float*)d_in[8];
    const float* b3 = (const float*)d_in[9];
    const float* W4 = (const float*)d_in[10];
    const float* b4 = (const float*)d_in[11];
    float* out = (float*)d_out;

    int nodes = in_sizes[1] / AEMB;
    int grid  = nodes / 128;

    cudaFuncSetAttribute(tp_head_kernel,
                         cudaFuncAttributeMaxDynamicSharedMemorySize, SMEM_BYTES);
    tp_head_kernel<<<grid, NTH, SMEM_BYTES>>>(nv, ae, W1, b1, W2, b2,
                                              W3, b3, W4, b4, out);
}

// round 12
// speedup vs baseline: 2.0797x; 1.1480x over previous
#include <cuda_runtime.h>
#include <math.h>

#define NTH  512
#define AEMB 16
#define DIN  480

// ---- shared memory layout (float offsets) ----
#define X0P  132
#define ASP  17
#define AS_OFF  (128 * X0P)              // 16896
#define B1_OFF  (AS_OFF + 128 * ASP)     // 19072
#define B2_OFF  (B1_OFF + 128)           // 19200
#define WB_OFF  (B2_OFF + 16)            // 19216 (byte 76864, 16B aligned)
#define MID_OFF (WB_OFF + 2 * 8192)      // 35600
#define SMEM_FLOATS (MID_OFF + 128 * 17) // 37776
#define SMEM_BYTES  (SMEM_FLOATS * 4)    // 151104

typedef unsigned long long ull;

// Pre-packed weights (fp16 pairs in MMA fragment order)
// W1p: [i(128)][tile(16)][lane(32)][h(2)]  = 131072 u32 (chunk sc = 8192 u32)
// W2p: [i(128)][tile(2)][lane(32)][h(2)]   = 16384 u32  (chunk cN = 2048 u32)
__device__ unsigned g_W1p[131072];
__device__ unsigned g_W2p[16384];

__device__ __forceinline__ unsigned pkh2(float lo, float hi) {
    unsigned d;
    asm("cvt.rn.f16x2.f32 %0, %2, %1;" : "=r"(d) : "f"(lo), "f"(hi));
    return d;
}
__device__ __forceinline__ void mma16(float* d, unsigned a0, unsigned a1,
                                      unsigned a2, unsigned a3,
                                      unsigned b0, unsigned b1) {
    asm volatile(
        "mma.sync.aligned.m16n8k16.row.col.f32.f16.f16.f32 "
        "{%0,%1,%2,%3}, {%4,%5,%6,%7}, {%8,%9}, {%0,%1,%2,%3};"
        : "+f"(d[0]), "+f"(d[1]), "+f"(d[2]), "+f"(d[3])
        : "r"(a0), "r"(a1), "r"(a2), "r"(a3), "r"(b0), "r"(b1));
}
__device__ __forceinline__ void cpa16(unsigned s, const void* g) {
    asm volatile(
        "{ .reg .u64 ga; cvta.to.global.u64 ga, %1;"
        "  cp.async.cg.shared.global [%0], [ga], 16; }"
        :: "r"(s), "l"(g) : "memory");
}
#define CPA_COMMIT() asm volatile("cp.async.commit_group;" ::: "memory")
#define CPA_WAIT1()  asm volatile("cp.async.wait_group 1;" ::: "memory")
__device__ __forceinline__ unsigned smem_u32(const void* p) {
    unsigned a;
    asm("{ .reg .u64 t; cvta.to.shared.u64 t, %1; cvt.u32.u64 %0, t; }" : "=r"(a) : "l"(p));
    return a;
}
__device__ __forceinline__ float silu_f(float x) { return x / (1.0f + __expf(-x)); }

// ---------------- pre-pack kernel ----------------
__global__ void __launch_bounds__(256, 4)
pack_kernel(const float* __restrict__ W1, const float* __restrict__ W2) {
    int tid = blockIdx.x * 256 + threadIdx.x;
    if (tid < 131072) {
        int h = tid & 1, ll = (tid >> 1) & 31, t = (tid >> 6) & 15, i = tid >> 10;
        int q = ll >> 2, mk = ll & 3;
        int n = t * 8 + q, kr = h * 8 + 2 * mk;
        const float* p = W1 + ((size_t)(i * 16 + kr)) * 224 + n;
        g_W1p[tid] = pkh2(p[0], p[224]);
    } else {
        int t2 = tid - 131072;
        if (t2 < 16384) {
            int h = t2 & 1, ll = (t2 >> 1) & 31, tt = (t2 >> 6) & 1, i = t2 >> 7;
            int q = ll >> 2, mk = ll & 3;
            int n = tt * 8 + q, kr = h * 8 + 2 * mk;
            const float* p = W2 + ((size_t)(i * 16 + kr)) * 16 + n;
            g_W2p[t2] = pkh2(p[0], p[16]);
        }
    }
}

// ---------------- main kernel ----------------
__global__ void __launch_bounds__(NTH, 1)
tp_head_kernel(const float* __restrict__ nv, const float* __restrict__ ae,
               const float* __restrict__ b1, const float* __restrict__ b2,
               const float* __restrict__ W3, const float* __restrict__ b3,
               const float* __restrict__ W4, const float* __restrict__ b4,
               float* __restrict__ out)
{
    extern __shared__ float sm[];
    float*    x0s  = sm;                        // [128][132] x0, later scalars
    float*    as_  = sm + AS_OFF;               // [128][17]
    float*    b1s  = sm + B1_OFF;
    float*    b2s  = sm + B2_OFF;
    unsigned* wb32 = (unsigned*)(sm + WB_OFF);  // 2 x 8192 u32 B buffers
    float*    wbf  = sm + WB_OFF;               // float view (phase 3)
    float*    mids = sm + MID_OFF;              // [128][17]

    const int tid = threadIdx.x;
    const int wid = tid >> 5;
    const int l   = tid & 31;
    const int n0  = blockIdx.x * 128;
    const int q   = l >> 2;
    const int mk  = l & 3;

    const unsigned wbB = smem_u32(wb32);        // byte addr of buffer 0

    // ---- stage x0 (first 128 cols), a, b1, b2; start W1 chunk-0 copy ----
    {   // W1 chunk 0 -> buf 0
        const unsigned* src = g_W1p + tid * 4;
        unsigned d = wbB + tid * 16;
        cpa16(d,         src);
        cpa16(d + 8192,  src + 2048);
        cpa16(d + 16384, src + 4096);
        cpa16(d + 24576, src + 6144);
        CPA_COMMIT();
    }
    for (int t = tid; t < 128 * 32; t += NTH) {
        int lr = t >> 5, c4 = (t & 31) << 2;
        float4 v = *(const float4*)(nv + (size_t)(n0 + lr) * DIN + c4);
        *(float4*)(x0s + lr * X0P + c4) = v;
    }
    {
        int lr = tid >> 2, c4 = (tid & 3) << 2;
        float4 v = *(const float4*)(ae + (size_t)(n0 + lr) * AEMB + c4);
        float* dst = as_ + lr * ASP + c4;
        dst[0] = v.x; dst[1] = v.y; dst[2] = v.z; dst[3] = v.w;
    }
    if (tid < 128) b1s[tid] = b1[tid];
    if (tid >= 128 && tid < 144) b2s[tid - 128] = b2[tid - 128];
    __syncthreads();

    // ---- MMA geometry: warp = 32 rows (rp) x 32 cols (nq) ----
    const int rp = wid >> 2;
    const int nq = wid & 3;
    float ar[4][4];
#pragma unroll
    for (int j = 0; j < 4; ++j) {
        int rj = rp * 32 + q + j * 8;
        ar[j][0] = as_[rj * ASP + 2 * mk];
        ar[j][1] = as_[rj * ASP + 2 * mk + 1];
        ar[j][2] = as_[rj * ASP + 2 * mk + 8];
        ar[j][3] = as_[rj * ASP + 2 * mk + 9];
    }
    float acc[8][4];
#pragma unroll
    for (int t = 0; t < 8; ++t)
#pragma unroll
        for (int e = 0; e < 4; ++e) acc[t][e] = 0.0f;

    // =============== Phase 1: 16 chunks of 8 i ===============
    for (int sc = 0; sc < 16; ++sc) {
        if (sc + 1 < 16) {  // issue next chunk into other buffer
            const unsigned* src = g_W1p + (sc + 1) * 8192 + tid * 4;
            unsigned d = wbB + ((sc + 1) & 1) * 32768 + tid * 16;
            cpa16(d,         src);
            cpa16(d + 8192,  src + 2048);
            cpa16(d + 16384, src + 4096);
            cpa16(d + 24576, src + 6144);
        }
        CPA_COMMIT();
        CPA_WAIT1();
        __syncthreads();

        const unsigned* bb = wb32 + (sc & 1) * 8192;
#pragma unroll
        for (int ib = 0; ib < 2; ++ib) {
            float xr[4][4];
#pragma unroll
            for (int j = 0; j < 4; ++j) {
                float4 v = *(const float4*)(x0s + (rp * 32 + q + j * 8) * X0P
                                                + sc * 8 + ib * 4);
                xr[j][0] = v.x; xr[j][1] = v.y; xr[j][2] = v.z; xr[j][3] = v.w;
            }
#pragma unroll
            for (int i4 = 0; i4 < 4; ++i4) {
                int il = ib * 4 + i4;
                float x0v = xr[0][i4], x1v = xr[1][i4];
                float x2v = xr[2][i4], x3v = xr[3][i4];
                unsigned A0[4], A1[4];
                A0[0] = pkh2(x0v * ar[0][0], x0v * ar[0][1]);
                A0[1] = pkh2(x1v * ar[1][0], x1v * ar[1][1]);
                A0[2] = pkh2(x0v * ar[0][2], x0v * ar[0][3]);
                A0[3] = pkh2(x1v * ar[1][2], x1v * ar[1][3]);
                A1[0] = pkh2(x2v * ar[2][0], x2v * ar[2][1]);
                A1[1] = pkh2(x3v * ar[3][0], x3v * ar[3][1]);
                A1[2] = pkh2(x2v * ar[2][2], x2v * ar[2][3]);
                A1[3] = pkh2(x3v * ar[3][2], x3v * ar[3][3]);
                const ull* bp = (const ull*)bb + (il * 16 + nq * 4) * 32 + l;
#pragma unroll
                for (int t = 0; t < 4; ++t) {
                    ull bv = bp[t * 32];
                    unsigned bx0, bx1;
                    asm("mov.b64 {%0,%1}, %2;" : "=r"(bx0), "=r"(bx1) : "l"(bv));
                    mma16(acc[t],     A0[0], A0[1], A0[2], A0[3], bx0, bx1);
                    mma16(acc[4 + t], A1[0], A1[1], A1[2], A1[3], bx0, bx1);
                }
            }
        }
        __syncthreads();
    }

    // ---- epilogue 1: scalars = silu(s*INV + b1) -> x0s ----
    const float INV = 0.022097086912079608f;   // 1/sqrt(128*16)
#pragma unroll
    for (int sp = 0; sp < 2; ++sp)
#pragma unroll
        for (int t = 0; t < 4; ++t) {
            int c0 = nq * 32 + t * 8 + mk * 2;
            int row = rp * 32 + sp * 16 + q;
            float* a = acc[sp * 4 + t];
            x0s[row * X0P + c0]           = silu_f(a[0] * INV + b1s[c0]);
            x0s[row * X0P + c0 + 1]       = silu_f(a[1] * INV + b1s[c0 + 1]);
            x0s[(row + 8) * X0P + c0]     = silu_f(a[2] * INV + b1s[c0]);
            x0s[(row + 8) * X0P + c0 + 1] = silu_f(a[3] * INV + b1s[c0 + 1]);
        }

    // ---- phase-2 MMA geometry: warp = 16 rows (sW) x 8 cols (th) ----
    const int sW = wid >> 1;
    const int th = wid & 1;
    float ar2[2][4];
#pragma unroll
    for (int j = 0; j < 2; ++j) {
        int rj = sW * 16 + q + j * 8;
        ar2[j][0] = as_[rj * ASP + 2 * mk];
        ar2[j][1] = as_[rj * ASP + 2 * mk + 1];
        ar2[j][2] = as_[rj * ASP + 2 * mk + 8];
        ar2[j][3] = as_[rj * ASP + 2 * mk + 9];
    }
    float acc2[4] = {0.0f, 0.0f, 0.0f, 0.0f};

    // prologue: W2 chunk 0 -> buf 0
    cpa16(wbB + tid * 16, g_W2p + tid * 4);
    CPA_COMMIT();

    // =============== Phase 2: 8 chunks of 16 i ===============
    for (int cN = 0; cN < 8; ++cN) {
        if (cN + 1 < 8)
            cpa16(wbB + ((cN + 1) & 1) * 32768 + tid * 16,
                  g_W2p + (cN + 1) * 2048 + tid * 4);
        CPA_COMMIT();
        CPA_WAIT1();
        __syncthreads();

        const unsigned* bb = wb32 + (cN & 1) * 8192;
#pragma unroll
        for (int ib = 0; ib < 4; ++ib) {
            float xr0[4], xr1[4];
            {
                float4 v = *(const float4*)(x0s + (sW * 16 + q) * X0P
                                                + cN * 16 + ib * 4);
                xr0[0] = v.x; xr0[1] = v.y; xr0[2] = v.z; xr0[3] = v.w;
                v = *(const float4*)(x0s + (sW * 16 + 8 + q) * X0P
                                         + cN * 16 + ib * 4);
                xr1[0] = v.x; xr1[1] = v.y; xr1[2] = v.z; xr1[3] = v.w;
            }
#pragma unroll
            for (int i4 = 0; i4 < 4; ++i4) {
                int il = ib * 4 + i4;
                float s0 = xr0[i4], s1 = xr1[i4];
                unsigned a0 = pkh2(s0 * ar2[0][0], s0 * ar2[0][1]);
                unsigned a1 = pkh2(s1 * ar2[1][0], s1 * ar2[1][1]);
                unsigned a2 = pkh2(s0 * ar2[0][2], s0 * ar2[0][3]);
                unsigned a3 = pkh2(s1 * ar2[1][2], s1 * ar2[1][3]);
                ull bv = ((const ull*)bb)[(il * 2 + th) * 32 + l];
                unsigned bx0, bx1;
                asm("mov.b64 {%0,%1}, %2;" : "=r"(bx0), "=r"(bx1) : "l"(bv));
                mma16(acc2, a0, a1, a2, a3, bx0, bx1);
            }
        }
        __syncthreads();
    }

    // ---- epilogue 2 ----
    {
        int c0 = th * 8 + mk * 2;
        int row = sW * 16 + q;
        mids[row * 17 + c0]           = acc2[0] * INV + b2s[c0];
        mids[row * 17 + c0 + 1]       = acc2[1] * INV + b2s[c0 + 1];
        mids[(row + 8) * 17 + c0]     = acc2[2] * INV + b2s[c0];
        mids[(row + 8) * 17 + c0 + 1] = acc2[3] * INV + b2s[c0 + 1];
    }
    __syncthreads();

    // stage W3/W4/b3/b4 into wbf (B buffers dead now)
    if (tid < 256) wbf[tid] = W3[tid];
    if (tid >= 256 && tid < 272) wbf[tid] = W4[tid - 256];
    if (tid >= 288 && tid < 304) wbf[tid] = b3[tid - 288];
    if (tid == 304) wbf[304] = b4[0];
    __syncthreads();

    // =============== Phase 3: tiny 16x16 head ===============
    if (tid < 128) {
        float mv[16];
#pragma unroll
        for (int j = 0; j < 16; ++j) mv[j] = mids[tid * 17 + j];
        float o = 0.0f;
#pragma unroll
        for (int jo = 0; jo < 16; ++jo) {
            float t = 0.0f;
#pragma unroll
            for (int ji = 0; ji < 16; ++ji) t += mv[ji] * wbf[ji * 16 + jo];
            t = t * 0.25f + wbf[288 + jo];
            o += silu_f(t) * wbf[256 + jo];
        }
        out[n0 + tid] = o * 0.25f + wbf[304];
    }
}

extern "C" void kernel_launch(void* const* d_in, const int* in_sizes, int n_in,
                              void* d_out, int out_size) {
    const float* nv = (const float*)d_in[0];
    const float* ae = (const float*)d_in[1];
    const float* W1 = (const float*)d_in[2];
    // d_in[3], d_in[4] dead (W1_l1, W1_l2)
    const float* b1 = (const float*)d_in[5];
    const float* W2 = (const float*)d_in[6];
    const float* b2 = (const float*)d_in[7];
    const float* W3 = (const float*)d_in[8];
    const float* b3 = (const float*)d_in[9];
    const float* W4 = (const float*)d_in[10];
    const float* b4 = (const float*)d_in[11];
    float* out = (float*)d_out;

    int nodes = in_sizes[1] / AEMB;
    int grid  = nodes / 128;

    pack_kernel<<<576, 256>>>(W1, W2);

    cudaFuncSetAttribute(tp_head_kernel,
                         cudaFuncAttributeMaxDynamicSharedMemorySize, SMEM_BYTES);
    tp_head_kernel<<<grid, NTH, SMEM_BYTES>>>(nv, ae, b1, b2,
                                              W3, b3, W4, b4, out);
}

// round 13
// speedup vs baseline: 2.1090x; 1.0141x over previous
#include <cuda_runtime.h>
#include <math.h>

#define NTH  256
#define BM   64
#define AEMB 16
#define DIN  480

// ---- shared memory layout (float offsets) ----
#define X0P  132
#define ASP  17
#define AS_OFF  (BM * X0P)               // 8448
#define B1_OFF  (AS_OFF + BM * ASP)      // 9536
#define B2_OFF  (B1_OFF + 128)           // 9664
#define WB_OFF  (B2_OFF + 16)            // 9680 (byte 38720, 16B aligned)
#define MID_OFF (WB_OFF + 2 * 8192)      // 26064
#define SMEM_FLOATS (MID_OFF + BM * 17)  // 27152
#define SMEM_BYTES  (SMEM_FLOATS * 4)    // 108608  -> 2 CTAs/SM (217KB < 228KB)

typedef unsigned long long ull;

// Pre-packed weights (fp16 pairs in MMA fragment order)
// W1p: [i(128)][tile(16)][lane(32)][h(2)]  = 131072 u32 (chunk of 8 i = 8192 u32)
// W2p: [i(128)][tile(2)][lane(32)][h(2)]   = 16384 u32  (chunk of 16 i = 2048 u32)
__device__ unsigned g_W1p[131072];
__device__ unsigned g_W2p[16384];

__device__ __forceinline__ unsigned pkh2(float lo, float hi) {
    unsigned d;
    asm("cvt.rn.f16x2.f32 %0, %2, %1;" : "=r"(d) : "f"(lo), "f"(hi));
    return d;
}
__device__ __forceinline__ void mma16(float* d, unsigned a0, unsigned a1,
                                      unsigned a2, unsigned a3,
                                      unsigned b0, unsigned b1) {
    asm volatile(
        "mma.sync.aligned.m16n8k16.row.col.f32.f16.f16.f32 "
        "{%0,%1,%2,%3}, {%4,%5,%6,%7}, {%8,%9}, {%0,%1,%2,%3};"
        : "+f"(d[0]), "+f"(d[1]), "+f"(d[2]), "+f"(d[3])
        : "r"(a0), "r"(a1), "r"(a2), "r"(a3), "r"(b0), "r"(b1));
}
__device__ __forceinline__ void cpa16(unsigned s, const void* g) {
    asm volatile(
        "{ .reg .u64 ga; cvta.to.global.u64 ga, %1;"
        "  cp.async.cg.shared.global [%0], [ga], 16; }"
        :: "r"(s), "l"(g) : "memory");
}
#define CPA_COMMIT() asm volatile("cp.async.commit_group;" ::: "memory")
#define CPA_WAIT1()  asm volatile("cp.async.wait_group 1;" ::: "memory")
__device__ __forceinline__ unsigned smem_u32(const void* p) {
    unsigned a;
    asm("{ .reg .u64 t; cvta.to.shared.u64 t, %1; cvt.u32.u64 %0, t; }" : "=r"(a) : "l"(p));
    return a;
}
__device__ __forceinline__ float silu_f(float x) { return x / (1.0f + __expf(-x)); }

// ---------------- pre-pack kernel (layouts unchanged from R12) ----------------
__global__ void __launch_bounds__(256, 4)
pack_kernel(const float* __restrict__ W1, const float* __restrict__ W2) {
    int tid = blockIdx.x * 256 + threadIdx.x;
    if (tid < 131072) {
        int h = tid & 1, ll = (tid >> 1) & 31, t = (tid >> 6) & 15, i = tid >> 10;
        int q = ll >> 2, mk = ll & 3;
        int n = t * 8 + q, kr = h * 8 + 2 * mk;
        const float* p = W1 + ((size_t)(i * 16 + kr)) * 224 + n;
        g_W1p[tid] = pkh2(p[0], p[224]);
    } else {
        int t2 = tid - 131072;
        if (t2 < 16384) {
            int h = t2 & 1, ll = (t2 >> 1) & 31, tt = (t2 >> 6) & 1, i = t2 >> 7;
            int q = ll >> 2, mk = ll & 3;
            int n = tt * 8 + q, kr = h * 8 + 2 * mk;
            const float* p = W2 + ((size_t)(i * 16 + kr)) * 16 + n;
            g_W2p[t2] = pkh2(p[0], p[16]);
        }
    }
}

// ---------------- main kernel ----------------
__global__ void __launch_bounds__(NTH, 2)
tp_head_kernel(const float* __restrict__ nv, const float* __restrict__ ae,
               const float* __restrict__ b1, const float* __restrict__ b2,
               const float* __restrict__ W3, const float* __restrict__ b3,
               const float* __restrict__ W4, const float* __restrict__ b4,
               float* __restrict__ out)
{
    extern __shared__ float sm[];
    float*    x0s  = sm;                        // [64][132] x0, later scalars
    float*    as_  = sm + AS_OFF;               // [64][17]
    float*    b1s  = sm + B1_OFF;
    float*    b2s  = sm + B2_OFF;
    unsigned* wb32 = (unsigned*)(sm + WB_OFF);  // 2 x 8192 u32 B buffers
    float*    wbf  = sm + WB_OFF;               // float view (phase 3)
    float*    mids = sm + MID_OFF;              // [64][17]

    const int tid = threadIdx.x;
    const int wid = tid >> 5;
    const int l   = tid & 31;
    const int n0  = blockIdx.x * BM;
    const int q   = l >> 2;
    const int mk  = l & 3;

    const unsigned wbB = smem_u32(wb32);

    // ---- start W1 chunk-0 copy; stage x0, a, b1, b2 ----
    {   // chunk 0 -> buf 0: 8192 u32 / 256 thr = 32 u32 = 8 x 16B per thread
        const unsigned* src = g_W1p + tid * 4;
        unsigned d = wbB + tid * 16;
#pragma unroll
        for (int g = 0; g < 8; ++g)
            cpa16(d + g * 4096, src + g * 1024);
        CPA_COMMIT();
    }
    for (int t = tid; t < BM * 32; t += NTH) {
        int lr = t >> 5, c4 = (t & 31) << 2;
        float4 v = *(const float4*)(nv + (size_t)(n0 + lr) * DIN + c4);
        *(float4*)(x0s + lr * X0P + c4) = v;
    }
    if (tid < BM * 4) {
        int lr = tid >> 2, c4 = (tid & 3) << 2;
        float4 v = *(const float4*)(ae + (size_t)(n0 + lr) * AEMB + c4);
        float* dst = as_ + lr * ASP + c4;
        dst[0] = v.x; dst[1] = v.y; dst[2] = v.z; dst[3] = v.w;
    }
    if (tid < 128) b1s[tid] = b1[tid];
    if (tid >= 128 && tid < 144) b2s[tid - 128] = b2[tid - 128];
    __syncthreads();

    // ---- phase-1 MMA geometry: warp = 16 rows (rs) x 64 cols (cg: tiles cg*8..+7) ----
    const int rs = wid >> 1;          // row strip 0..3
    const int cg = wid & 1;           // col group 0..1
    float ar[2][4];                   // a[row_j][{2mk,2mk+1,2mk+8,2mk+9}]
#pragma unroll
    for (int j = 0; j < 2; ++j) {
        int rj = rs * 16 + q + j * 8;
        ar[j][0] = as_[rj * ASP + 2 * mk];
        ar[j][1] = as_[rj * ASP + 2 * mk + 1];
        ar[j][2] = as_[rj * ASP + 2 * mk + 8];
        ar[j][3] = as_[rj * ASP + 2 * mk + 9];
    }
    float acc[8][4];
#pragma unroll
    for (int t = 0; t < 8; ++t)
#pragma unroll
        for (int e = 0; e < 4; ++e) acc[t][e] = 0.0f;

    // =============== Phase 1: 16 chunks of 8 i ===============
    for (int sc = 0; sc < 16; ++sc) {
        if (sc + 1 < 16) {
            const unsigned* src = g_W1p + (sc + 1) * 8192 + tid * 4;
            unsigned d = wbB + ((sc + 1) & 1) * 32768 + tid * 16;
#pragma unroll
            for (int g = 0; g < 8; ++g)
                cpa16(d + g * 4096, src + g * 1024);
        }
        CPA_COMMIT();
        CPA_WAIT1();
        __syncthreads();

        const unsigned* bb = wb32 + (sc & 1) * 8192;
#pragma unroll
        for (int ib = 0; ib < 2; ++ib) {
            float xr[2][4];
#pragma unroll
            for (int j = 0; j < 2; ++j) {
                float4 v = *(const float4*)(x0s + (rs * 16 + q + j * 8) * X0P
                                                + sc * 8 + ib * 4);
                xr[j][0] = v.x; xr[j][1] = v.y; xr[j][2] = v.z; xr[j][3] = v.w;
            }
#pragma unroll
            for (int i4 = 0; i4 < 4; ++i4) {
                int il = ib * 4 + i4;
                float x0v = xr[0][i4], x1v = xr[1][i4];
                unsigned A0 = pkh2(x0v * ar[0][0], x0v * ar[0][1]);
                unsigned A1 = pkh2(x1v * ar[1][0], x1v * ar[1][1]);
                unsigned A2 = pkh2(x0v * ar[0][2], x0v * ar[0][3]);
                unsigned A3 = pkh2(x1v * ar[1][2], x1v * ar[1][3]);
                const ull* bp = (const ull*)bb + (il * 16 + cg * 8) * 32 + l;
#pragma unroll
                for (int t = 0; t < 8; ++t) {
                    ull bv = bp[t * 32];
                    unsigned bx0, bx1;
                    asm("mov.b64 {%0,%1}, %2;" : "=r"(bx0), "=r"(bx1) : "l"(bv));
                    mma16(acc[t], A0, A1, A2, A3, bx0, bx1);
                }
            }
        }
        __syncthreads();
    }

    // ---- epilogue 1: scalars = silu(s*INV + b1) -> x0s ----
    const float INV = 0.022097086912079608f;   // 1/sqrt(128*16)
#pragma unroll
    for (int t = 0; t < 8; ++t) {
        int c0 = cg * 64 + t * 8 + mk * 2;
        int row = rs * 16 + q;
        float* a = acc[t];
        x0s[row * X0P + c0]           = silu_f(a[0] * INV + b1s[c0]);
        x0s[row * X0P + c0 + 1]       = silu_f(a[1] * INV + b1s[c0 + 1]);
        x0s[(row + 8) * X0P + c0]     = silu_f(a[2] * INV + b1s[c0]);
        x0s[(row + 8) * X0P + c0 + 1] = silu_f(a[3] * INV + b1s[c0 + 1]);
    }

    // ---- phase-2 MMA geometry: warp = 16 rows (sW) x 8 cols (th) ----
    const int sW = wid >> 1;
    const int th = wid & 1;
    float acc2[4] = {0.0f, 0.0f, 0.0f, 0.0f};

    // prologue: W2 chunk 0 -> buf 0 (2048 u32 / 256 thr = 2 x 16B)
    cpa16(wbB + tid * 16, g_W2p + tid * 4);
    cpa16(wbB + 4096 + tid * 16, g_W2p + 1024 + tid * 4);
    CPA_COMMIT();

    // =============== Phase 2: 8 chunks of 16 i ===============
    for (int cN = 0; cN < 8; ++cN) {
        if (cN + 1 < 8) {
            const unsigned* src = g_W2p + (cN + 1) * 2048 + tid * 4;
            unsigned d = wbB + ((cN + 1) & 1) * 32768 + tid * 16;
            cpa16(d, src);
            cpa16(d + 4096, src + 1024);
        }
        CPA_COMMIT();
        CPA_WAIT1();
        __syncthreads();

        const unsigned* bb = wb32 + (cN & 1) * 8192;
#pragma unroll
        for (int ib = 0; ib < 4; ++ib) {
            float xr0[4], xr1[4];
            {
                float4 v = *(const float4*)(x0s + (sW * 16 + q) * X0P
                                                + cN * 16 + ib * 4);
                xr0[0] = v.x; xr0[1] = v.y; xr0[2] = v.z; xr0[3] = v.w;
                v = *(const float4*)(x0s + (sW * 16 + 8 + q) * X0P
                                         + cN * 16 + ib * 4);
                xr1[0] = v.x; xr1[1] = v.y; xr1[2] = v.z; xr1[3] = v.w;
            }
#pragma unroll
            for (int i4 = 0; i4 < 4; ++i4) {
                int il = ib * 4 + i4;
                float s0 = xr0[i4], s1 = xr1[i4];
                unsigned a0 = pkh2(s0 * ar[0][0], s0 * ar[0][1]);
                unsigned a1 = pkh2(s1 * ar[1][0], s1 * ar[1][1]);
                unsigned a2 = pkh2(s0 * ar[0][2], s0 * ar[0][3]);
                unsigned a3 = pkh2(s1 * ar[1][2], s1 * ar[1][3]);
                ull bv = ((const ull*)bb)[(il * 2 + th) * 32 + l];
                unsigned bx0, bx1;
                asm("mov.b64 {%0,%1}, %2;" : "=r"(bx0), "=r"(bx1) : "l"(bv));
                mma16(acc2, a0, a1, a2, a3, bx0, bx1);
            }
        }
        __syncthreads();
    }

    // ---- epilogue 2 ----
    {
        int c0 = th * 8 + mk * 2;
        int row = sW * 16 + q;
        mids[row * 17 + c0]           = acc2[0] * INV + b2s[c0];
        mids[row * 17 + c0 + 1]       = acc2[1] * INV + b2s[c0 + 1];
        mids[(row + 8) * 17 + c0]     = acc2[2] * INV + b2s[c0];
        mids[(row + 8) * 17 + c0 + 1] = acc2[3] * INV + b2s[c0 + 1];
    }
    __syncthreads();

    // stage W3/W4/b3/b4 into wbf (B buffers dead now)
    if (tid < 256) wbf[tid] = W3[tid];
    if (tid < 16)  { wbf[256 + tid] = W4[tid]; wbf[288 + tid] = b3[tid]; }
    if (tid == 0)  wbf[304] = b4[0];
    __syncthreads();

    // =============== Phase 3: tiny 16x16 head ===============
    if (tid < BM) {
        float mv[16];
#pragma unroll
        for (int j = 0; j < 16; ++j) mv[j] = mids[tid * 17 + j];
        float o = 0.0f;
#pragma unroll
        for (int jo = 0; jo < 16; ++jo) {
            float t = 0.0f;
#pragma unroll
            for (int ji = 0; ji < 16; ++ji) t += mv[ji] * wbf[ji * 16 + jo];
            t = t * 0.25f + wbf[288 + jo];
            o += silu_f(t) * wbf[256 + jo];
        }
        out[n0 + tid] = o * 0.25f + wbf[304];
    }
}

extern "C" void kernel_launch(void* const* d_in, const int* in_sizes, int n_in,
                              void* d_out, int out_size) {
    const float* nv = (const float*)d_in[0];
    const float* ae = (const float*)d_in[1];
    const float* W1 = (const float*)d_in[2];
    // d_in[3], d_in[4] dead (W1_l1, W1_l2)
    const float* b1 = (const float*)d_in[5];
    const float* W2 = (const float*)d_in[6];
    const float* b2 = (const float*)d_in[7];
    const float* W3 = (const float*)d_in[8];
    const float* b3 = (const float*)d_in[9];
    const float* W4 = (const float*)d_in[10];
    const float* b4 = (const float*)d_in[11];
    float* out = (float*)d_out;

    int nodes = in_sizes[1] / AEMB;
    int grid  = nodes / BM;

    pack_kernel<<<576, 256>>>(W1, W2);

    cudaFuncSetAttribute(tp_head_kernel,
                         cudaFuncAttributeMaxDynamicSharedMemorySize, SMEM_BYTES);
    tp_head_kernel<<<grid, NTH, SMEM_BYTES>>>(nv, ae, b1, b2,
                                              W3, b3, W4, b4, out);
}